// round 6
// baseline (speedup 1.0000x reference)
#include <cuda_runtime.h>
#include <cuda_fp16.h>
#include <cstdint>
#include <cstddef>

#define B_  64
#define T_  1024
#define F_  512
#define H_  512
#define G4_ 2048   // 4H
#define NCTA 128

__device__ float  g_xproj[(size_t)T_ * B_ * G4_];        // [t][b][col] fp32
__device__ __half g_hbuf[2][B_ * H_];                    // [b][k] fp16, double-buffered
__device__ unsigned g_flags[NCTA * 32];                  // 1 flag per 128B line
__device__ __half g_ah[(size_t)B_ * T_ * F_];            // inputs as fp16 [m][k]
__device__ __half g_bh[(size_t)G4_ * F_];                // Wx^T hi fp16 [n][k]
__device__ __half g_bl[(size_t)G4_ * F_];                // Wx^T lo fp16 [n][k]

// ---------------------------------------------------------------------------
__device__ __forceinline__ void cp16(void* dst, const void* src)
{
    unsigned d = (unsigned)__cvta_generic_to_shared(dst);
    asm volatile("cp.async.cg.shared.global [%0], [%1], 16;" :: "r"(d), "l"(src) : "memory");
}

__device__ __forceinline__ unsigned ld_acq(const unsigned* p)
{
    unsigned v;
    asm volatile("ld.acquire.gpu.global.u32 %0, [%1];" : "=r"(v) : "l"(p) : "memory");
    return v;
}

__device__ __forceinline__ void st_rel(unsigned* p, unsigned v)
{
    asm volatile("st.release.gpu.global.u32 [%0], %1;" :: "l"(p), "r"(v) : "memory");
}

__device__ __forceinline__ unsigned pack2(float a, float b)
{
    __half2 h = __floats2half2_rn(a, b);   // low=a, high=b
    return *(unsigned*)&h;
}

__device__ __forceinline__ void mma16(float* c,
    unsigned a0, unsigned a1, unsigned a2, unsigned a3,
    unsigned b0, unsigned b1)
{
    asm volatile(
        "mma.sync.aligned.m16n8k16.row.col.f32.f16.f16.f32 "
        "{%0,%1,%2,%3}, {%4,%5,%6,%7}, {%8,%9}, {%0,%1,%2,%3};"
        : "+f"(c[0]), "+f"(c[1]), "+f"(c[2]), "+f"(c[3])
        : "r"(a0), "r"(a1), "r"(a2), "r"(a3), "r"(b0), "r"(b1));
}

// ---------------------------------------------------------------------------
// Prep kernels: convert inputs -> fp16 [m][k]; Wx -> transposed fp16 hi/lo [n][k]
// ---------------------------------------------------------------------------
__global__ void __launch_bounds__(256) conv_a(const float* __restrict__ A)
{
    unsigned i0 = blockIdx.x * 256 + threadIdx.x;
#pragma unroll
    for (int j = 0; j < 8; j++) {
        unsigned i = i0 + j * (8192u * 256u);        // 16777216 float2 total
        float2 v = ((const float2*)A)[i];
        ((unsigned*)g_ah)[i] = pack2(v.x, v.y);
    }
}

__global__ void __launch_bounds__(256) conv_b(const float* __restrict__ W)
{
    unsigned i = blockIdx.x * 256 + threadIdx.x;     // over 1048576 elems
    int k = i >> 11, n = i & 2047;
    float w = W[i];
    __half hi = __float2half_rn(w);
    float lo = w - __half2float(hi);
    g_bh[(size_t)n * 512 + k] = hi;
    g_bl[(size_t)n * 512 + k] = __float2half_rn(lo);
}

// ---------------------------------------------------------------------------
// Kernel 1: x_proj = inputs @ Wx + bias, fp16 MMA (A fp16, B = hi+lo fp16).
// CTA tile 128x128, stage k=32, double-buffered. 8 warps (2m x 4n).
// smem halves, row stride 40 (32 + 8 pad) -> conflict-free single-LDS frags.
// ---------------------------------------------------------------------------
#define GSTG 15360        // halves per stage: Ah 5120 | Bh 5120 | Bl 5120

__global__ void __launch_bounds__(256) gemm_xproj(const float* __restrict__ bias)
{
    extern __shared__ __half smh[];

    const int tid = threadIdx.x;
    const int n0  = blockIdx.x * 128;
    const int m0  = blockIdx.y * 128;
    const int warp = tid >> 5, lane = tid & 31;
    const int wm = warp & 1, wn = warp >> 1;
    const int r  = lane >> 2, cq = lane & 3;

    float acc[4][4][4];
#pragma unroll
    for (int i = 0; i < 4; i++)
#pragma unroll
        for (int j = 0; j < 4; j++)
#pragma unroll
            for (int k = 0; k < 4; k++) acc[i][j][k] = 0.f;

    auto issue = [&](int s, int bi) {
        __half* Ad = smh + bi * GSTG;
        __half* Bh = Ad + 5120;
        __half* Bl = Ad + 10240;
#pragma unroll
        for (int j = 0; j < 2; j++) {
            int q = tid + j * 256;                 // 512 cp16 for A
            int row = q >> 2, seg = q & 3;
            cp16(Ad + row * 40 + seg * 8,
                 g_ah + (size_t)(m0 + row) * 512 + s * 32 + seg * 8);
        }
#pragma unroll
        for (int j = 0; j < 2; j++) {
            int q = tid + j * 256;
            int row = q >> 2, seg = q & 3;
            cp16(Bh + row * 40 + seg * 8,
                 g_bh + (size_t)(n0 + row) * 512 + s * 32 + seg * 8);
        }
#pragma unroll
        for (int j = 0; j < 2; j++) {
            int q = tid + j * 256;
            int row = q >> 2, seg = q & 3;
            cp16(Bl + row * 40 + seg * 8,
                 g_bl + (size_t)(n0 + row) * 512 + s * 32 + seg * 8);
        }
        asm volatile("cp.async.commit_group;" ::: "memory");
    };

    issue(0, 0);

    for (int s = 0; s < 16; s++) {
        if (s < 15) {
            issue(s + 1, (s + 1) & 1);
            asm volatile("cp.async.wait_group 1;" ::: "memory");
        } else {
            asm volatile("cp.async.wait_group 0;" ::: "memory");
        }
        __syncthreads();

        const __half* Ab  = smh + (s & 1) * GSTG + (wm * 64) * 40;
        const __half* Bhb = smh + (s & 1) * GSTG + 5120  + (wn * 32) * 40;
        const __half* Blb = smh + (s & 1) * GSTG + 10240 + (wn * 32) * 40;

#pragma unroll
        for (int kk = 0; kk < 32; kk += 16) {
            unsigned a[4][4];
#pragma unroll
            for (int mt = 0; mt < 4; mt++) {
                const __half* ap = Ab + (mt * 16 + r) * 40 + kk + 2 * cq;
                a[mt][0] = *(const unsigned*)(ap);
                a[mt][1] = *(const unsigned*)(ap + 8 * 40);
                a[mt][2] = *(const unsigned*)(ap + 8);
                a[mt][3] = *(const unsigned*)(ap + 8 * 40 + 8);
            }
            unsigned bH[4][2], bL[4][2];
#pragma unroll
            for (int nt = 0; nt < 4; nt++) {
                const __half* bph = Bhb + (nt * 8 + r) * 40 + kk + 2 * cq;
                const __half* bpl = Blb + (nt * 8 + r) * 40 + kk + 2 * cq;
                bH[nt][0] = *(const unsigned*)(bph);
                bH[nt][1] = *(const unsigned*)(bph + 8);
                bL[nt][0] = *(const unsigned*)(bpl);
                bL[nt][1] = *(const unsigned*)(bpl + 8);
            }
#pragma unroll
            for (int nt = 0; nt < 4; nt++)
#pragma unroll
                for (int mt = 0; mt < 4; mt++)
                    mma16(acc[mt][nt], a[mt][0], a[mt][1], a[mt][2], a[mt][3],
                          bH[nt][0], bH[nt][1]);
#pragma unroll
            for (int nt = 0; nt < 4; nt++)
#pragma unroll
                for (int mt = 0; mt < 4; mt++)
                    mma16(acc[mt][nt], a[mt][0], a[mt][1], a[mt][2], a[mt][3],
                          bL[nt][0], bL[nt][1]);
        }
        __syncthreads();
    }

    const int mbase = m0 + wm * 64;
    const int nbase = n0 + wn * 32;
#pragma unroll
    for (int nt = 0; nt < 4; nt++) {
        int nn = nbase + nt * 8 + cq * 2;
        float2 bb = *(const float2*)(bias + nn);
#pragma unroll
        for (int mt = 0; mt < 4; mt++) {
            int row0 = mbase + mt * 16 + r;
            int t0 = row0 & (T_ - 1), bi0 = row0 >> 10;
            float2 v0 = make_float2(acc[mt][nt][0] + bb.x, acc[mt][nt][1] + bb.y);
            *(float2*)&g_xproj[((size_t)(t0 * 64 + bi0) << 11) + nn] = v0;
            int row1 = row0 + 8;
            int t1 = row1 & (T_ - 1), bi1 = row1 >> 10;
            float2 v1 = make_float2(acc[mt][nt][2] + bb.x, acc[mt][nt][3] + bb.y);
            *(float2*)&g_xproj[((size_t)(t1 * 64 + bi1) << 11) + nn] = v1;
        }
    }
}

// ---------------------------------------------------------------------------
// Kernel 2: persistent LSTM recurrence, fp16 h + fp16 2-term Wh MMA.
// h stored [b][k] fp16 (64 KB/step broadcast). Chunks = 4 x (k=128) slabs;
// warp w copies AND consumes k columns [128ch+16w, +16) -> warp-local ring,
// no block syncs in the chunk loop. Wh frags (hi+lo half2) in regs.
// ---------------------------------------------------------------------------
#define SHH_STRIDE 136                    // halves per b-row in a chunk (128+8)
#define SHH_CHUNK (64 * SHH_STRIDE)       // halves per chunk buffer
#define SG_STRIDE 18
#define SG_WARP  (64 * SG_STRIDE)

__global__ void __launch_bounds__(256, 1) lstm_kernel(
    const float* __restrict__ Wh,
    float* __restrict__ out)
{
    extern __shared__ char smraw[];
    __half* shh = (__half*)smraw;                          // 3 * 64*136 halves = 52224 B
    float*  sg  = (float*)(smraw + 3 * SHH_CHUNK * 2);     // 8 * 64*18 floats = 36864 B
    float*  sx  = (float*)(smraw + 3 * SHH_CHUNK * 2 + 8 * SG_WARP * 4); // 2*1024 floats

    const int tid = threadIdx.x;
    const int cta = blockIdx.x;
    const int warp = tid >> 5, lane = tid & 31;
    const int r = lane >> 2, cq = lane & 3;

    const unsigned base = ld_acq(&g_flags[cta * 32]);

    // Preload Wh fragments (hi + lo fp16) into registers.
    // Warp w owns k16-tile w of each 128-k chunk c: k0 = 128c + 16w.
    unsigned BH[4][2][2], BL[4][2][2];
#pragma unroll
    for (int c = 0; c < 4; c++) {
        int k0 = c * 128 + warp * 16;
#pragma unroll
        for (int nt = 0; nt < 2; nt++) {
            int n = nt * 8 + r;
            int col = ((n >> 2) << 9) + (cta << 2) + (n & 3);
            float w00 = Wh[(size_t)(k0 + 2 * cq)     * G4_ + col];
            float w01 = Wh[(size_t)(k0 + 2 * cq + 1) * G4_ + col];
            float w10 = Wh[(size_t)(k0 + 2 * cq + 8) * G4_ + col];
            float w11 = Wh[(size_t)(k0 + 2 * cq + 9) * G4_ + col];
            __half h00 = __float2half_rn(w00), h01 = __float2half_rn(w01);
            __half h10 = __float2half_rn(w10), h11 = __float2half_rn(w11);
            BH[c][nt][0] = pack2(w00, w01);
            BH[c][nt][1] = pack2(w10, w11);
            BL[c][nt][0] = pack2(w00 - __half2float(h00), w01 - __half2float(h01));
            BL[c][nt][1] = pack2(w10 - __half2float(h10), w11 - __half2float(h11));
        }
    }

    // zero h buffer 0 (16384 uints over 128 CTAs)
    if (tid < 128) ((unsigned*)g_hbuf[0])[cta * 128 + tid] = 0u;

    // prefetch x_proj(t=0) into sx[0]
    {
        int b = tid >> 2, g = tid & 3;
        cp16(sx + b * 16 + g * 4,
             g_xproj + ((size_t)b << 11) + ((size_t)g << 9) + (cta << 2));
        asm volatile("cp.async.commit_group;" ::: "memory");
        asm volatile("cp.async.wait_group 0;" ::: "memory");
    }

    __syncthreads();
    {   // barrier 0: init complete
        unsigned tgt = base + 1;
        if (tid == 0) st_rel(&g_flags[cta * 32], tgt);
        if (tid < NCTA)
            while ((int)(ld_acq(&g_flags[tid * 32]) - tgt) < 0) {}
        __syncthreads();
    }

    const int eb = tid >> 2, ej = tid & 3;    // cell-update mapping
    float c_reg = 0.f;

    // warp-local chunk copy: warp w copies k cols [128ch+16w, +16) for all 64 b.
    auto issue_chunk = [&](const __half* hsrc, int ch) {
        __half* dst = shh + (ch % 3) * SHH_CHUNK + warp * 16;
        const __half* src = hsrc + ch * 128 + warp * 16;
#pragma unroll
        for (int i = 0; i < 4; i++) {
            int idx = lane + 32 * i;              // 0..127
            int b = idx >> 1, s_ = idx & 1;
            cp16(dst + b * SHH_STRIDE + s_ * 8, src + (size_t)b * 512 + s_ * 8);
        }
    };

    for (int t = 0; t < T_; t++) {
        const __half* hsrc = g_hbuf[t & 1];

        issue_chunk(hsrc, 0);
        asm volatile("cp.async.commit_group;" ::: "memory");
        issue_chunk(hsrc, 1);
        asm volatile("cp.async.commit_group;" ::: "memory");

        float acc[4][2][4];
#pragma unroll
        for (int mt = 0; mt < 4; mt++)
#pragma unroll
            for (int nt = 0; nt < 2; nt++)
#pragma unroll
                for (int k = 0; k < 4; k++) acc[mt][nt][k] = 0.f;

#pragma unroll
        for (int ch = 0; ch < 4; ch++) {
            if (ch < 3) { asm volatile("cp.async.wait_group 1;" ::: "memory"); }
            else        { asm volatile("cp.async.wait_group 0;" ::: "memory"); }
            __syncwarp();

            if (ch == 0) {
                issue_chunk(hsrc, 2);
                if (t + 1 < T_) {
                    int b = tid >> 2, g = tid & 3;
                    cp16(sx + ((t + 1) & 1) * 1024 + b * 16 + g * 4,
                         g_xproj + ((size_t)((t + 1) * 64 + b) << 11)
                                 + ((size_t)g << 9) + (cta << 2));
                }
                asm volatile("cp.async.commit_group;" ::: "memory");
            } else if (ch == 1) {
                issue_chunk(hsrc, 3);
                asm volatile("cp.async.commit_group;" ::: "memory");
            }

            const __half* hb = shh + (ch % 3) * SHH_CHUNK + warp * 16 + 2 * cq;
            unsigned a[4][4];
#pragma unroll
            for (int mt = 0; mt < 4; mt++) {
                const __half* ap = hb + (mt * 16 + r) * SHH_STRIDE;
                a[mt][0] = *(const unsigned*)(ap);
                a[mt][1] = *(const unsigned*)(ap + 8 * SHH_STRIDE);
                a[mt][2] = *(const unsigned*)(ap + 8);
                a[mt][3] = *(const unsigned*)(ap + 8 * SHH_STRIDE + 8);
            }
#pragma unroll
            for (int nt = 0; nt < 2; nt++)
#pragma unroll
                for (int mt = 0; mt < 4; mt++)
                    mma16(acc[mt][nt], a[mt][0], a[mt][1], a[mt][2], a[mt][3],
                          BH[ch][nt][0], BH[ch][nt][1]);
#pragma unroll
            for (int nt = 0; nt < 2; nt++)
#pragma unroll
                for (int mt = 0; mt < 4; mt++)
                    mma16(acc[mt][nt], a[mt][0], a[mt][1], a[mt][2], a[mt][3],
                          BL[ch][nt][0], BL[ch][nt][1]);
        }

        // split-k partials -> smem
        {
            float* sgp = sg + warp * SG_WARP;
#pragma unroll
            for (int mt = 0; mt < 4; mt++) {
                int b0 = mt * 16 + r;
#pragma unroll
                for (int nt = 0; nt < 2; nt++) {
                    int n = nt * 8 + cq * 2;
                    *(float2*)&sgp[b0 * SG_STRIDE + n] =
                        make_float2(acc[mt][nt][0], acc[mt][nt][1]);
                    *(float2*)&sgp[(b0 + 8) * SG_STRIDE + n] =
                        make_float2(acc[mt][nt][2], acc[mt][nt][3]);
                }
            }
        }
        __syncthreads();

        // cell update: thread -> (eb, ej); gates i,f,g,o at n = g*4 + ej
        {
            const float* sxb = sx + (t & 1) * 1024;
            float v[4];
#pragma unroll
            for (int g = 0; g < 4; g++) {
                int n = (g << 2) + ej;
                float s = sxb[eb * 16 + n];
#pragma unroll
                for (int w = 0; w < 8; w++) s += sg[w * SG_WARP + eb * SG_STRIDE + n];
                v[g] = s;
            }
            float si = 1.f / (1.f + __expf(-v[0]));
            float sf = 1.f / (1.f + __expf(-v[1]));
            float tg = tanhf(v[2]);
            float so = 1.f / (1.f + __expf(-v[3]));
            c_reg = sf * c_reg + si * tg;
            float hn = so * tanhf(c_reg);

            // pack 4 gate-cols (ej 0..3) of this b into one 8B fp16 store
            float n1 = __shfl_down_sync(0xffffffffu, hn, 1);
            float n2 = __shfl_down_sync(0xffffffffu, hn, 2);
            float n3 = __shfl_down_sync(0xffffffffu, hn, 3);
            if (ej == 0) {
                uint2 vst = make_uint2(pack2(hn, n1), pack2(n2, n3));
                *(uint2*)&g_hbuf[(t + 1) & 1][((size_t)eb << 9) + (cta << 2)] = vst;
            }

            if (t == T_ - 1) {
                int colj = (cta << 2) + ej;
                out[eb * H_ + colj]           = c_reg;   // c_fin
                out[B_ * H_ + eb * H_ + colj] = hn;      // h_fin
            }
        }

        __syncthreads();
        {   // grid barrier for step t
            unsigned tgt = base + 2 + (unsigned)t;
            if (tid == 0) st_rel(&g_flags[cta * 32], tgt);
            if (tid < NCTA)
                while ((int)(ld_acq(&g_flags[tid * 32]) - tgt) < 0) {}
            __syncthreads();
        }
    }
}

// ---------------------------------------------------------------------------
extern "C" void kernel_launch(void* const* d_in, const int* in_sizes, int n_in,
                              void* d_out, int out_size)
{
    const float* inputs = (const float*)d_in[0];  // [B, T, F]
    const float* Wx     = (const float*)d_in[1];  // [F, 4H]
    const float* Wh     = (const float*)d_in[2];  // [H, 4H]
    const float* bias   = (const float*)d_in[3];  // [4H]
    float* out = (float*)d_out;                   // [2, B, H] = (c_fin, h_fin)

    (void)in_sizes; (void)n_in; (void)out_size;

    conv_a<<<8192, 256>>>(inputs);
    conv_b<<<4096, 256>>>(Wx);

    const int gemm_smem = 2 * GSTG * (int)sizeof(__half);   // 61440 B
    cudaFuncSetAttribute(gemm_xproj, cudaFuncAttributeMaxDynamicSharedMemorySize, gemm_smem);
    gemm_xproj<<<dim3(G4_ / 128, (B_ * T_) / 128), 256, gemm_smem>>>(bias);

    const int lstm_smem = 3 * SHH_CHUNK * 2 + 8 * SG_WARP * 4 + 2 * 1024 * 4; // 97280 B
    cudaFuncSetAttribute(lstm_kernel, cudaFuncAttributeMaxDynamicSharedMemorySize, lstm_smem);
    lstm_kernel<<<NCTA, 256, lstm_smem>>>(Wh, out);
}

// round 7
// speedup vs baseline: 1.0113x; 1.0113x over previous
#include <cuda_runtime.h>
#include <cuda_fp16.h>
#include <cstdint>
#include <cstddef>

#define B_  64
#define T_  1024
#define F_  512
#define H_  512
#define G4_ 2048   // 4H
#define NCTA 128

__device__ float  g_xproj[(size_t)T_ * B_ * G4_];        // [t][b][col] fp32
__device__ float  g_hbuf[2][H_ * B_];                    // [col(k)][b] fp32, double-buffered
__device__ unsigned g_flags[NCTA * 32];                  // 1 flag per 128B line
__device__ __half g_ah[(size_t)B_ * T_ * F_];            // inputs as fp16 [m][k]
__device__ __half g_bh[(size_t)G4_ * F_];                // Wx^T hi fp16 [n][k]
__device__ __half g_bl[(size_t)G4_ * F_];                // Wx^T lo fp16 [n][k]

// ---------------------------------------------------------------------------
__device__ __forceinline__ void cp16(void* dst, const void* src)
{
    unsigned d = (unsigned)__cvta_generic_to_shared(dst);
    asm volatile("cp.async.cg.shared.global [%0], [%1], 16;" :: "r"(d), "l"(src) : "memory");
}

__device__ __forceinline__ unsigned ld_acq(const unsigned* p)
{
    unsigned v;
    asm volatile("ld.acquire.gpu.global.u32 %0, [%1];" : "=r"(v) : "l"(p) : "memory");
    return v;
}

__device__ __forceinline__ void st_rel(unsigned* p, unsigned v)
{
    asm volatile("st.release.gpu.global.u32 [%0], %1;" :: "l"(p), "r"(v) : "memory");
}

__device__ __forceinline__ unsigned pack2(float a, float b)
{
    __half2 h = __floats2half2_rn(a, b);
    return *(unsigned*)&h;
}

// lo part of the tf32 split: x - truncate_to_tf32(x)  (exact in fp32)
__device__ __forceinline__ float tf32_lo(float x)
{
    unsigned u = __float_as_uint(x) & 0xFFFFE000u;
    return x - __uint_as_float(u);
}

__device__ __forceinline__ void mma8(float* c,
    unsigned a0, unsigned a1, unsigned a2, unsigned a3,
    unsigned b0, unsigned b1)
{
    asm volatile(
        "mma.sync.aligned.m16n8k8.row.col.f32.tf32.tf32.f32 "
        "{%0,%1,%2,%3}, {%4,%5,%6,%7}, {%8,%9}, {%0,%1,%2,%3};"
        : "+f"(c[0]), "+f"(c[1]), "+f"(c[2]), "+f"(c[3])
        : "r"(a0), "r"(a1), "r"(a2), "r"(a3), "r"(b0), "r"(b1));
}

__device__ __forceinline__ void mma16(float* c,
    unsigned a0, unsigned a1, unsigned a2, unsigned a3,
    unsigned b0, unsigned b1)
{
    asm volatile(
        "mma.sync.aligned.m16n8k16.row.col.f32.f16.f16.f32 "
        "{%0,%1,%2,%3}, {%4,%5,%6,%7}, {%8,%9}, {%0,%1,%2,%3};"
        : "+f"(c[0]), "+f"(c[1]), "+f"(c[2]), "+f"(c[3])
        : "r"(a0), "r"(a1), "r"(a2), "r"(a3), "r"(b0), "r"(b1));
}

// ---------------------------------------------------------------------------
// Prep kernels (unchanged from R6)
// ---------------------------------------------------------------------------
__global__ void __launch_bounds__(256) conv_a(const float* __restrict__ A)
{
    unsigned i0 = blockIdx.x * 256 + threadIdx.x;
#pragma unroll
    for (int j = 0; j < 8; j++) {
        unsigned i = i0 + j * (8192u * 256u);
        float2 v = ((const float2*)A)[i];
        ((unsigned*)g_ah)[i] = pack2(v.x, v.y);
    }
}

__global__ void __launch_bounds__(256) conv_b(const float* __restrict__ W)
{
    unsigned i = blockIdx.x * 256 + threadIdx.x;
    int k = i >> 11, n = i & 2047;
    float w = W[i];
    __half hi = __float2half_rn(w);
    float lo = w - __half2float(hi);
    g_bh[(size_t)n * 512 + k] = hi;
    g_bl[(size_t)n * 512 + k] = __float2half_rn(lo);
}

// ---------------------------------------------------------------------------
// Kernel 1: x_proj GEMM, fp16 2-term (unchanged from R6)
// ---------------------------------------------------------------------------
#define GSTG 15360

__global__ void __launch_bounds__(256) gemm_xproj(const float* __restrict__ bias)
{
    extern __shared__ __half smh[];

    const int tid = threadIdx.x;
    const int n0  = blockIdx.x * 128;
    const int m0  = blockIdx.y * 128;
    const int warp = tid >> 5, lane = tid & 31;
    const int wm = warp & 1, wn = warp >> 1;
    const int r  = lane >> 2, cq = lane & 3;

    float acc[4][4][4];
#pragma unroll
    for (int i = 0; i < 4; i++)
#pragma unroll
        for (int j = 0; j < 4; j++)
#pragma unroll
            for (int k = 0; k < 4; k++) acc[i][j][k] = 0.f;

    auto issue = [&](int s, int bi) {
        __half* Ad = smh + bi * GSTG;
        __half* Bh = Ad + 5120;
        __half* Bl = Ad + 10240;
#pragma unroll
        for (int j = 0; j < 2; j++) {
            int q = tid + j * 256;
            int row = q >> 2, seg = q & 3;
            cp16(Ad + row * 40 + seg * 8,
                 g_ah + (size_t)(m0 + row) * 512 + s * 32 + seg * 8);
        }
#pragma unroll
        for (int j = 0; j < 2; j++) {
            int q = tid + j * 256;
            int row = q >> 2, seg = q & 3;
            cp16(Bh + row * 40 + seg * 8,
                 g_bh + (size_t)(n0 + row) * 512 + s * 32 + seg * 8);
        }
#pragma unroll
        for (int j = 0; j < 2; j++) {
            int q = tid + j * 256;
            int row = q >> 2, seg = q & 3;
            cp16(Bl + row * 40 + seg * 8,
                 g_bl + (size_t)(n0 + row) * 512 + s * 32 + seg * 8);
        }
        asm volatile("cp.async.commit_group;" ::: "memory");
    };

    issue(0, 0);

    for (int s = 0; s < 16; s++) {
        if (s < 15) {
            issue(s + 1, (s + 1) & 1);
            asm volatile("cp.async.wait_group 1;" ::: "memory");
        } else {
            asm volatile("cp.async.wait_group 0;" ::: "memory");
        }
        __syncthreads();

        const __half* Ab  = smh + (s & 1) * GSTG + (wm * 64) * 40;
        const __half* Bhb = smh + (s & 1) * GSTG + 5120  + (wn * 32) * 40;
        const __half* Blb = smh + (s & 1) * GSTG + 10240 + (wn * 32) * 40;

#pragma unroll
        for (int kk = 0; kk < 32; kk += 16) {
            unsigned a[4][4];
#pragma unroll
            for (int mt = 0; mt < 4; mt++) {
                const __half* ap = Ab + (mt * 16 + r) * 40 + kk + 2 * cq;
                a[mt][0] = *(const unsigned*)(ap);
                a[mt][1] = *(const unsigned*)(ap + 8 * 40);
                a[mt][2] = *(const unsigned*)(ap + 8);
                a[mt][3] = *(const unsigned*)(ap + 8 * 40 + 8);
            }
            unsigned bH[4][2], bL[4][2];
#pragma unroll
            for (int nt = 0; nt < 4; nt++) {
                const __half* bph = Bhb + (nt * 8 + r) * 40 + kk + 2 * cq;
                const __half* bpl = Blb + (nt * 8 + r) * 40 + kk + 2 * cq;
                bH[nt][0] = *(const unsigned*)(bph);
                bH[nt][1] = *(const unsigned*)(bph + 8);
                bL[nt][0] = *(const unsigned*)(bpl);
                bL[nt][1] = *(const unsigned*)(bpl + 8);
            }
#pragma unroll
            for (int nt = 0; nt < 4; nt++)
#pragma unroll
                for (int mt = 0; mt < 4; mt++)
                    mma16(acc[mt][nt], a[mt][0], a[mt][1], a[mt][2], a[mt][3],
                          bH[nt][0], bH[nt][1]);
#pragma unroll
            for (int nt = 0; nt < 4; nt++)
#pragma unroll
                for (int mt = 0; mt < 4; mt++)
                    mma16(acc[mt][nt], a[mt][0], a[mt][1], a[mt][2], a[mt][3],
                          bL[nt][0], bL[nt][1]);
        }
        __syncthreads();
    }

    const int mbase = m0 + wm * 64;
    const int nbase = n0 + wn * 32;
#pragma unroll
    for (int nt = 0; nt < 4; nt++) {
        int nn = nbase + nt * 8 + cq * 2;
        float2 bb = *(const float2*)(bias + nn);
#pragma unroll
        for (int mt = 0; mt < 4; mt++) {
            int row0 = mbase + mt * 16 + r;
            int t0 = row0 & (T_ - 1), bi0 = row0 >> 10;
            float2 v0 = make_float2(acc[mt][nt][0] + bb.x, acc[mt][nt][1] + bb.y);
            *(float2*)&g_xproj[((size_t)(t0 * 64 + bi0) << 11) + nn] = v0;
            int row1 = row0 + 8;
            int t1 = row1 & (T_ - 1), bi1 = row1 >> 10;
            float2 v1 = make_float2(acc[mt][nt][2] + bb.x, acc[mt][nt][3] + bb.y);
            *(float2*)&g_xproj[((size_t)(t1 * 64 + bi1) << 11) + nn] = v1;
        }
    }
}

// ---------------------------------------------------------------------------
// Kernel 2: persistent LSTM recurrence — R5 datapath (fp32 h [col][b],
// tf32 2-term register Wh), NEW pipelined producer-group exchange:
// chunk ch's producers are CTAs 32ch..32ch+32; each warp polls those 32 flags
// (1/lane) right before issuing that chunk's cp.async. No end-of-step global
// barrier. Ring-reuse safe: reaching cell(t) requires observing all 128
// producer flags of step t, which implies all CTAs finished reading h(t-1).
// ---------------------------------------------------------------------------
#define SH_STRIDE 72
#define SH_CHUNK (128 * SH_STRIDE)
#define SG_STRIDE 18
#define SG_WARP  (64 * SG_STRIDE)

__global__ void __launch_bounds__(256, 1) lstm_kernel(
    const float* __restrict__ Wh,
    float* __restrict__ out)
{
    extern __shared__ float smem[];
    float* sh = smem;                    // 3 * 128*72 = 27648 floats
    float* sg = sh + 3 * SH_CHUNK;       // 8 * 64*18  =  9216 floats
    float* sx = sg + 8 * SG_WARP;        // 2 * 1024   =  2048 floats

    const int tid = threadIdx.x;
    const int cta = blockIdx.x;
    const int warp = tid >> 5, lane = tid & 31;
    const int r = lane >> 2, cq = lane & 3;

    const unsigned base = ld_acq(&g_flags[cta * 32]);

    // Preload Wh fragments (hi + lo tf32) into registers (R5 mapping):
    // warp w owns global ktiles {16c + 8j + w}.
    unsigned BH[16][2], BL[16][2];
#pragma unroll
    for (int c = 0; c < 4; c++)
#pragma unroll
        for (int j = 0; j < 2; j++) {
            int kt = c * 16 + j * 8 + warp;
            int k0 = kt << 3;
#pragma unroll
            for (int nt = 0; nt < 2; nt++) {
                int n = nt * 8 + r;
                int col = ((n >> 2) << 9) + (cta << 2) + (n & 3);
                float w0 = Wh[(size_t)(k0 + cq) * G4_ + col];
                float w1 = Wh[(size_t)(k0 + cq + 4) * G4_ + col];
                int bi = (c << 2) | (j << 1) | nt;
                BH[bi][0] = __float_as_uint(w0);
                BH[bi][1] = __float_as_uint(w1);
                BL[bi][0] = __float_as_uint(tf32_lo(w0));
                BL[bi][1] = __float_as_uint(tf32_lo(w1));
            }
        }

    g_hbuf[0][(cta << 8) + tid] = 0.f;

    // prefetch x_proj(t=0) into sx[0]
    {
        int b = tid >> 2, g = tid & 3;
        cp16(sx + b * 16 + g * 4,
             g_xproj + ((size_t)b << 11) + ((size_t)g << 9) + (cta << 2));
        asm volatile("cp.async.commit_group;" ::: "memory");
        asm volatile("cp.async.wait_group 0;" ::: "memory");
    }

    __syncthreads();
    {   // barrier 0: init complete (full barrier once)
        unsigned tgt = base + 1;
        if (tid == 0) st_rel(&g_flags[cta * 32], tgt);
        if (tid < NCTA)
            while ((int)(ld_acq(&g_flags[tid * 32]) - tgt) < 0) {}
        __syncthreads();
    }

    const int eb = tid >> 2, ej = tid & 3;
    const int colj = (cta << 2) + ej;
    float c_reg = 0.f;

    // warp-local chunk copy: warp loads exactly its own 16 rows (2x8) per chunk.
    auto issue_chunk = [&](const float* hsrc, int ch) {
        const int buf = ch % 3;
#pragma unroll
        for (int j = 0; j < 2; j++) {
            const float* s0 = hsrc + (size_t)(ch * 128 + j * 64 + warp * 8) * 64;
            float* d0 = sh + buf * SH_CHUNK + (j * 64 + warp * 8) * SH_STRIDE;
#pragma unroll
            for (int i = 0; i < 4; i++) {
                int s_ = lane + 32 * i;
                int row8 = s_ >> 4, segc = s_ & 15;
                cp16(d0 + row8 * SH_STRIDE + segc * 4, s0 + row8 * 64 + segc * 4);
            }
        }
    };

    // per-warp poll of chunk ch's 32 producer CTAs (CTAs 32ch..32ch+31)
    auto poll_group = [&](int ch, unsigned tgt) {
        const unsigned* f = &g_flags[((ch << 5) + lane) << 5];
        while ((int)(ld_acq(f) - tgt) < 0) {}
        __syncwarp();
    };

    // mma on chunk ch (reads buf ch%3)
    auto do_mma = [&](int ch, float acc[4][2][4]) {
        const float* hb = sh + (ch % 3) * SH_CHUNK;
#pragma unroll
        for (int j = 0; j < 2; j++) {
            const int lk0 = ((j << 3) + warp) << 3;
            unsigned a[4][4];
#pragma unroll
            for (int mt = 0; mt < 4; mt++) {
                const float* ap = hb + (lk0 + cq) * SH_STRIDE + mt * 16 + r;
                a[mt][0] = __float_as_uint(ap[0]);
                a[mt][1] = __float_as_uint(ap[8]);
                a[mt][2] = __float_as_uint(ap[4 * SH_STRIDE]);
                a[mt][3] = __float_as_uint(ap[4 * SH_STRIDE + 8]);
            }
            const int bi0 = (ch << 2) | (j << 1);
#pragma unroll
            for (int nt = 0; nt < 2; nt++)
#pragma unroll
                for (int mt = 0; mt < 4; mt++)
                    mma8(acc[mt][nt], a[mt][0], a[mt][1], a[mt][2], a[mt][3],
                         BH[bi0 | nt][0], BH[bi0 | nt][1]);
#pragma unroll
            for (int nt = 0; nt < 2; nt++)
#pragma unroll
                for (int mt = 0; mt < 4; mt++)
                    mma8(acc[mt][nt], a[mt][0], a[mt][1], a[mt][2], a[mt][3],
                         BL[bi0 | nt][0], BL[bi0 | nt][1]);
        }
    };

    for (int t = 0; t < T_; t++) {
        const float* hsrc = g_hbuf[t & 1];
        const unsigned tgt = base + 1 + (unsigned)t;   // producers' step-t level

        float acc[4][2][4];
#pragma unroll
        for (int mt = 0; mt < 4; mt++)
#pragma unroll
            for (int nt = 0; nt < 2; nt++)
#pragma unroll
                for (int k = 0; k < 4; k++) acc[mt][nt][k] = 0.f;

        // prologue: poll+issue chunks 0,1
        poll_group(0, tgt);
        issue_chunk(hsrc, 0);
        asm volatile("cp.async.commit_group;" ::: "memory");
        poll_group(1, tgt);
        issue_chunk(hsrc, 1);
        asm volatile("cp.async.commit_group;" ::: "memory");

        // ch 0
        poll_group(2, tgt);
        issue_chunk(hsrc, 2);
        if (t + 1 < T_) {
            int b = tid >> 2, g = tid & 3;
            cp16(sx + ((t + 1) & 1) * 1024 + b * 16 + g * 4,
                 g_xproj + ((size_t)((t + 1) * 64 + b) << 11)
                         + ((size_t)g << 9) + (cta << 2));
        }
        asm volatile("cp.async.commit_group;" ::: "memory");
        asm volatile("cp.async.wait_group 2;" ::: "memory");
        __syncwarp();
        do_mma(0, acc);

        // ch 1
        poll_group(3, tgt);
        issue_chunk(hsrc, 3);
        asm volatile("cp.async.commit_group;" ::: "memory");
        asm volatile("cp.async.wait_group 2;" ::: "memory");
        __syncwarp();
        do_mma(1, acc);

        // ch 2
        asm volatile("cp.async.wait_group 1;" ::: "memory");
        __syncwarp();
        do_mma(2, acc);

        // ch 3
        asm volatile("cp.async.wait_group 0;" ::: "memory");
        __syncwarp();
        do_mma(3, acc);

        // split-k partials -> smem
        {
            float* sgp = sg + warp * SG_WARP;
#pragma unroll
            for (int mt = 0; mt < 4; mt++) {
                int b0 = mt * 16 + r;
#pragma unroll
                for (int nt = 0; nt < 2; nt++) {
                    int n = nt * 8 + cq * 2;
                    *(float2*)&sgp[b0 * SG_STRIDE + n] =
                        make_float2(acc[mt][nt][0], acc[mt][nt][1]);
                    *(float2*)&sgp[(b0 + 8) * SG_STRIDE + n] =
                        make_float2(acc[mt][nt][2], acc[mt][nt][3]);
                }
            }
        }
        __syncthreads();

        // cell update
        {
            const float* sxb = sx + (t & 1) * 1024;
            float v[4];
#pragma unroll
            for (int g = 0; g < 4; g++) {
                int n = (g << 2) + ej;
                float s = sxb[eb * 16 + n];
#pragma unroll
                for (int w = 0; w < 8; w++) s += sg[w * SG_WARP + eb * SG_STRIDE + n];
                v[g] = s;
            }
            float si = 1.f / (1.f + __expf(-v[0]));
            float sf = 1.f / (1.f + __expf(-v[1]));
            float tg = tanhf(v[2]);
            float so = 1.f / (1.f + __expf(-v[3]));
            c_reg = sf * c_reg + si * tg;
            float hn = so * tanhf(c_reg);

            g_hbuf[(t + 1) & 1][(colj << 6) + eb] = hn;

            if (t == T_ - 1) {
                out[eb * H_ + colj]           = c_reg;   // c_fin
                out[B_ * H_ + eb * H_ + colj] = hn;      // h_fin
            }
        }

        __syncthreads();   // all h-writes of this CTA done
        if (tid == 0) st_rel(&g_flags[cta * 32], base + 2 + (unsigned)t);
    }
}

// ---------------------------------------------------------------------------
extern "C" void kernel_launch(void* const* d_in, const int* in_sizes, int n_in,
                              void* d_out, int out_size)
{
    const float* inputs = (const float*)d_in[0];  // [B, T, F]
    const float* Wx     = (const float*)d_in[1];  // [F, 4H]
    const float* Wh     = (const float*)d_in[2];  // [H, 4H]
    const float* bias   = (const float*)d_in[3];  // [4H]
    float* out = (float*)d_out;                   // [2, B, H] = (c_fin, h_fin)

    (void)in_sizes; (void)n_in; (void)out_size;

    conv_a<<<8192, 256>>>(inputs);
    conv_b<<<4096, 256>>>(Wx);

    const int gemm_smem = 2 * GSTG * (int)sizeof(__half);
    cudaFuncSetAttribute(gemm_xproj, cudaFuncAttributeMaxDynamicSharedMemorySize, gemm_smem);
    gemm_xproj<<<dim3(G4_ / 128, (B_ * T_) / 128), 256, gemm_smem>>>(bias);

    const int lstm_smem = (3 * SH_CHUNK + 8 * SG_WARP + 2 * 1024) * (int)sizeof(float); // 155648 B
    cudaFuncSetAttribute(lstm_kernel, cudaFuncAttributeMaxDynamicSharedMemorySize, lstm_smem);
    lstm_kernel<<<NCTA, 256, lstm_smem>>>(Wh, out);
}

// round 9
// speedup vs baseline: 1.1510x; 1.1381x over previous
#include <cuda_runtime.h>
#include <cuda_fp16.h>
#include <cstdint>
#include <cstddef>

#define B_  64
#define T_  1024
#define F_  512
#define H_  512
#define G4_ 2048   // 4H
#define NCTA 128

__device__ float  g_xproj[(size_t)T_ * B_ * G4_];        // [t][b][col] fp32
__device__ float  g_hbuf[2][H_ * B_];                    // [col(k)][b] fp32, double-buffered
__device__ unsigned g_flags[NCTA * 32];                  // 1 flag per 128B line
__device__ __half g_ah[(size_t)B_ * T_ * F_];            // inputs as fp16 [m][k]
__device__ __half g_bh[(size_t)G4_ * F_];                // Wx^T hi fp16 [n][k]
__device__ __half g_bl[(size_t)G4_ * F_];                // Wx^T lo fp16 [n][k]

// ---------------------------------------------------------------------------
// helpers
// ---------------------------------------------------------------------------
__device__ __forceinline__ void cp16(void* dst, const void* src)
{
    unsigned d = (unsigned)__cvta_generic_to_shared(dst);
    asm volatile("cp.async.cg.shared.global [%0], [%1], 16;" :: "r"(d), "l"(src) : "memory");
}

__device__ __forceinline__ unsigned ld_acq(const unsigned* p)
{
    unsigned v;
    asm volatile("ld.acquire.gpu.global.u32 %0, [%1];" : "=r"(v) : "l"(p) : "memory");
    return v;
}

__device__ __forceinline__ void st_rel(unsigned* p, unsigned v)
{
    asm volatile("st.release.gpu.global.u32 [%0], %1;" :: "l"(p), "r"(v) : "memory");
}

__device__ __forceinline__ unsigned pack2(float a, float b)
{
    __half2 h = __floats2half2_rn(a, b);
    return *(unsigned*)&h;
}

// lo part of the tf32 split: x - truncate_to_tf32(x)  (exact in fp32)
__device__ __forceinline__ float tf32_lo(float x)
{
    unsigned u = __float_as_uint(x) & 0xFFFFE000u;
    return x - __uint_as_float(u);
}

__device__ __forceinline__ void mma8(float* c,
    unsigned a0, unsigned a1, unsigned a2, unsigned a3,
    unsigned b0, unsigned b1)
{
    asm volatile(
        "mma.sync.aligned.m16n8k8.row.col.f32.tf32.tf32.f32 "
        "{%0,%1,%2,%3}, {%4,%5,%6,%7}, {%8,%9}, {%0,%1,%2,%3};"
        : "+f"(c[0]), "+f"(c[1]), "+f"(c[2]), "+f"(c[3])
        : "r"(a0), "r"(a1), "r"(a2), "r"(a3), "r"(b0), "r"(b1));
}

__device__ __forceinline__ void mma16(float* c,
    unsigned a0, unsigned a1, unsigned a2, unsigned a3,
    unsigned b0, unsigned b1)
{
    asm volatile(
        "mma.sync.aligned.m16n8k16.row.col.f32.f16.f16.f32 "
        "{%0,%1,%2,%3}, {%4,%5,%6,%7}, {%8,%9}, {%0,%1,%2,%3};"
        : "+f"(c[0]), "+f"(c[1]), "+f"(c[2]), "+f"(c[3])
        : "r"(a0), "r"(a1), "r"(a2), "r"(a3), "r"(b0), "r"(b1));
}

__device__ __forceinline__ void ldmx4(unsigned* r, unsigned addr)
{
    asm volatile(
        "ldmatrix.sync.aligned.m8n8.x4.shared.b16 {%0,%1,%2,%3}, [%4];"
        : "=r"(r[0]), "=r"(r[1]), "=r"(r[2]), "=r"(r[3]) : "r"(addr));
}

__device__ __forceinline__ uint32_t smem_to_u32(const void* p) {
    uint32_t a;
    asm("{ .reg .u64 t; cvta.to.shared.u64 t, %1; cvt.u32.u64 %0, t; }"
        : "=r"(a) : "l"(p));
    return a;
}

// ---------------------------------------------------------------------------
// Prep kernels: inputs -> fp16 [m][k]; Wx -> transposed fp16 hi/lo [n][k]
// ---------------------------------------------------------------------------
__global__ void __launch_bounds__(256) conv_a(const float* __restrict__ A)
{
    unsigned i0 = blockIdx.x * 256 + threadIdx.x;
#pragma unroll
    for (int j = 0; j < 8; j++) {
        unsigned i = i0 + j * (8192u * 256u);
        float2 v = ((const float2*)A)[i];
        ((unsigned*)g_ah)[i] = pack2(v.x, v.y);
    }
}

__global__ void __launch_bounds__(256) conv_b(const float* __restrict__ W)
{
    unsigned i = blockIdx.x * 256 + threadIdx.x;
    int k = i >> 11, n = i & 2047;
    float w = W[i];
    __half hi = __float2half_rn(w);
    float lo = w - __half2float(hi);
    g_bh[(size_t)n * 512 + k] = hi;
    g_bl[(size_t)n * 512 + k] = __float2half_rn(lo);
}

// ---------------------------------------------------------------------------
// Kernel 1: x_proj = inputs @ Wx + bias — legacy fp16 mma, ldmatrix feeds,
// 3-stage cp.async ring, 1 syncthreads/stage, occupancy 2.
// CTA tile 128x128, 8 warps (2m x 4n), warp tile 64x32, k-stage = 32.
// smem rows: 32 halves @ 80B stride (16B aligned; banks 20r mod 32 ->
// conflict-free ldmatrix phases). Stage = A(10240) + Bh(10240) + Bl(10240).
// ---------------------------------------------------------------------------
#define GROW 80                         // bytes per 32-half row
#define GTILE (128 * GROW)              // 10240 B
#define GSTAGE (3 * GTILE)              // 30720 B
#define GHDR 1024
#define GSMEM (GHDR + 3 * GSTAGE)       // 93184 B

__global__ void __launch_bounds__(256, 2) gemm_f16(const float* __restrict__ bias)
{
    extern __shared__ char smc[];
    const unsigned sm32 = smem_to_u32(smc);

    const int tid = threadIdx.x;
    const int n0  = blockIdx.x * 128;
    const int m0  = blockIdx.y * 128;
    const int warp = tid >> 5, lane = tid & 31;
    const int wm = warp & 1, wn = warp >> 1;
    const int r  = lane >> 2, cq = lane & 3;
    const int lr = lane & 15, lh = lane >> 4;      // ldmatrix row / halfsel

    float* sbias = (float*)smc;
    if (tid < 128) sbias[tid] = bias[n0 + tid];

    float acc[4][4][4];
#pragma unroll
    for (int i = 0; i < 4; i++)
#pragma unroll
        for (int j = 0; j < 4; j++)
#pragma unroll
            for (int k = 0; k < 4; k++) acc[i][j][k] = 0.f;

    auto issue = [&](int s) {
        char* base = smc + GHDR + (s % 3) * GSTAGE;
#pragma unroll
        for (int i = 0; i < 6; i++) {
            int idx  = tid + i * 256;        // 0..1535
            int tile = idx >> 9;             // 0=A 1=Bh 2=Bl
            int q    = idx & 511;
            int row  = q >> 2, seg = q & 3;
            const __half* src =
                (tile == 0) ? g_ah + (size_t)(m0 + row) * 512 + s * 32 + seg * 8 :
                (tile == 1) ? g_bh + (size_t)(n0 + row) * 512 + s * 32 + seg * 8 :
                              g_bl + (size_t)(n0 + row) * 512 + s * 32 + seg * 8;
            cp16(base + tile * GTILE + row * GROW + seg * 16, src);
        }
        asm volatile("cp.async.commit_group;" ::: "memory");
    };

    issue(0);
    issue(1);

    for (int s = 0; s < 16; s++) {
        if (s < 15) { asm volatile("cp.async.wait_group 1;" ::: "memory"); }
        else        { asm volatile("cp.async.wait_group 0;" ::: "memory"); }
        __syncthreads();
        if (s + 2 < 16) issue(s + 2);     // safe: sync => all mma(s-1) done

        const unsigned sb = sm32 + GHDR + (s % 3) * GSTAGE;
        const unsigned Aad = sb + (wm * 64 + lr) * GROW + lh * 16;
        const unsigned Bad = sb + GTILE + (wn * 32 + lr) * GROW + lh * 16;

#pragma unroll
        for (int kk = 0; kk < 2; kk++) {
            unsigned a[4][4];
#pragma unroll
            for (int mt = 0; mt < 4; mt++)
                ldmx4(a[mt], Aad + mt * 16 * GROW + kk * 32);

            // B hi term
#pragma unroll
            for (int p = 0; p < 2; p++) {
                unsigned bq[4];
                ldmx4(bq, Bad + p * 16 * GROW + kk * 32);
#pragma unroll
                for (int mt = 0; mt < 4; mt++) {
                    mma16(acc[mt][2 * p],     a[mt][0], a[mt][1], a[mt][2], a[mt][3], bq[0], bq[2]);
                    mma16(acc[mt][2 * p + 1], a[mt][0], a[mt][1], a[mt][2], a[mt][3], bq[1], bq[3]);
                }
            }
            // B lo term
#pragma unroll
            for (int p = 0; p < 2; p++) {
                unsigned bq[4];
                ldmx4(bq, Bad + GTILE + p * 16 * GROW + kk * 32);
#pragma unroll
                for (int mt = 0; mt < 4; mt++) {
                    mma16(acc[mt][2 * p],     a[mt][0], a[mt][1], a[mt][2], a[mt][3], bq[0], bq[2]);
                    mma16(acc[mt][2 * p + 1], a[mt][0], a[mt][1], a[mt][2], a[mt][3], bq[1], bq[3]);
                }
            }
        }
    }

    const int mbase = m0 + wm * 64;
    const int nbase = n0 + wn * 32;
#pragma unroll
    for (int nt = 0; nt < 4; nt++) {
        int nn = nbase + nt * 8 + cq * 2;
        float2 bb = *(const float2*)(sbias + nt * 8 + cq * 2 + wn * 32);
#pragma unroll
        for (int mt = 0; mt < 4; mt++) {
            int row0 = mbase + mt * 16 + r;
            int t0 = row0 & (T_ - 1), bi0 = row0 >> 10;
            float2 v0 = make_float2(acc[mt][nt][0] + bb.x, acc[mt][nt][1] + bb.y);
            *(float2*)&g_xproj[((size_t)(t0 * 64 + bi0) << 11) + nn] = v0;
            int row1 = row0 + 8;
            int t1 = row1 & (T_ - 1), bi1 = row1 >> 10;
            float2 v1 = make_float2(acc[mt][nt][2] + bb.x, acc[mt][nt][3] + bb.y);
            *(float2*)&g_xproj[((size_t)(t1 * 64 + bi1) << 11) + nn] = v1;
        }
    }
}

// ---------------------------------------------------------------------------
// Kernel 2: persistent LSTM recurrence — VERBATIM best-known R5 config.
// ---------------------------------------------------------------------------
#define SH_STRIDE 72
#define SH_CHUNK (128 * SH_STRIDE)
#define SG_STRIDE 18
#define SG_WARP  (64 * SG_STRIDE)

__global__ void __launch_bounds__(256, 1) lstm_kernel(
    const float* __restrict__ Wh,
    float* __restrict__ out)
{
    extern __shared__ float smem[];
    float* sh = smem;                    // 3 * 128*72 = 27648 floats
    float* sg = sh + 3 * SH_CHUNK;       // 8 * 64*18  =  9216 floats
    float* sx = sg + 8 * SG_WARP;        // 2 * 1024   =  2048 floats

    const int tid = threadIdx.x;
    const int cta = blockIdx.x;
    const int warp = tid >> 5, lane = tid & 31;
    const int r = lane >> 2, cq = lane & 3;

    const unsigned base = ld_acq(&g_flags[cta * 32]);

    unsigned BH[16][2], BL[16][2];
#pragma unroll
    for (int c = 0; c < 4; c++)
#pragma unroll
        for (int j = 0; j < 2; j++) {
            int kt = c * 16 + j * 8 + warp;
            int k0 = kt << 3;
#pragma unroll
            for (int nt = 0; nt < 2; nt++) {
                int n = nt * 8 + r;
                int col = ((n >> 2) << 9) + (cta << 2) + (n & 3);
                float w0 = Wh[(size_t)(k0 + cq) * G4_ + col];
                float w1 = Wh[(size_t)(k0 + cq + 4) * G4_ + col];
                int bi = (c << 2) | (j << 1) | nt;
                BH[bi][0] = __float_as_uint(w0);
                BH[bi][1] = __float_as_uint(w1);
                BL[bi][0] = __float_as_uint(tf32_lo(w0));
                BL[bi][1] = __float_as_uint(tf32_lo(w1));
            }
        }

    g_hbuf[0][(cta << 8) + tid] = 0.f;

    {
        int b = tid >> 2, g = tid & 3;
        cp16(sx + b * 16 + g * 4,
             g_xproj + ((size_t)b << 11) + ((size_t)g << 9) + (cta << 2));
        asm volatile("cp.async.commit_group;" ::: "memory");
        asm volatile("cp.async.wait_group 0;" ::: "memory");
    }

    __syncthreads();
    {   // barrier 0: init complete
        unsigned tgt = base + 1;
        if (tid == 0) st_rel(&g_flags[cta * 32], tgt);
        if (tid < NCTA)
            while ((int)(ld_acq(&g_flags[tid * 32]) - tgt) < 0) {}
        __syncthreads();
    }

    const int eb = tid >> 2, ej = tid & 3;
    const int colj = (cta << 2) + ej;
    float c_reg = 0.f;

    auto issue_chunk = [&](const float* hsrc, int ch) {
        const int buf = ch % 3;
#pragma unroll
        for (int j = 0; j < 2; j++) {
            const float* s0 = hsrc + (size_t)(ch * 128 + j * 64 + warp * 8) * 64;
            float* d0 = sh + buf * SH_CHUNK + (j * 64 + warp * 8) * SH_STRIDE;
#pragma unroll
            for (int i = 0; i < 4; i++) {
                int s_ = lane + 32 * i;
                int row8 = s_ >> 4, segc = s_ & 15;
                cp16(d0 + row8 * SH_STRIDE + segc * 4, s0 + row8 * 64 + segc * 4);
            }
        }
    };

    for (int t = 0; t < T_; t++) {
        const float* hsrc = g_hbuf[t & 1];

        issue_chunk(hsrc, 0);
        asm volatile("cp.async.commit_group;" ::: "memory");
        issue_chunk(hsrc, 1);
        asm volatile("cp.async.commit_group;" ::: "memory");

        float acc[4][2][4];
#pragma unroll
        for (int mt = 0; mt < 4; mt++)
#pragma unroll
            for (int nt = 0; nt < 2; nt++)
#pragma unroll
                for (int k = 0; k < 4; k++) acc[mt][nt][k] = 0.f;

#pragma unroll
        for (int ch = 0; ch < 4; ch++) {
            if (ch < 3) { asm volatile("cp.async.wait_group 1;" ::: "memory"); }
            else        { asm volatile("cp.async.wait_group 0;" ::: "memory"); }
            __syncwarp();

            if (ch == 0) {
                issue_chunk(hsrc, 2);
                if (t + 1 < T_) {
                    int b = tid >> 2, g = tid & 3;
                    cp16(sx + ((t + 1) & 1) * 1024 + b * 16 + g * 4,
                         g_xproj + ((size_t)((t + 1) * 64 + b) << 11)
                                 + ((size_t)g << 9) + (cta << 2));
                }
                asm volatile("cp.async.commit_group;" ::: "memory");
            } else if (ch == 1) {
                issue_chunk(hsrc, 3);
                asm volatile("cp.async.commit_group;" ::: "memory");
            }

            const float* hb = sh + (ch % 3) * SH_CHUNK;
#pragma unroll
            for (int j = 0; j < 2; j++) {
                const int lk0 = ((j << 3) + warp) << 3;
                unsigned a[4][4];
#pragma unroll
                for (int mt = 0; mt < 4; mt++) {
                    const float* ap = hb + (lk0 + cq) * SH_STRIDE + mt * 16 + r;
                    a[mt][0] = __float_as_uint(ap[0]);
                    a[mt][1] = __float_as_uint(ap[8]);
                    a[mt][2] = __float_as_uint(ap[4 * SH_STRIDE]);
                    a[mt][3] = __float_as_uint(ap[4 * SH_STRIDE + 8]);
                }
                const int bi0 = (ch << 2) | (j << 1);
#pragma unroll
                for (int nt = 0; nt < 2; nt++)
#pragma unroll
                    for (int mt = 0; mt < 4; mt++)
                        mma8(acc[mt][nt], a[mt][0], a[mt][1], a[mt][2], a[mt][3],
                             BH[bi0 | nt][0], BH[bi0 | nt][1]);
#pragma unroll
                for (int nt = 0; nt < 2; nt++)
#pragma unroll
                    for (int mt = 0; mt < 4; mt++)
                        mma8(acc[mt][nt], a[mt][0], a[mt][1], a[mt][2], a[mt][3],
                             BL[bi0 | nt][0], BL[bi0 | nt][1]);
            }
        }

        {
            float* sgp = sg + warp * SG_WARP;
#pragma unroll
            for (int mt = 0; mt < 4; mt++) {
                int b0 = mt * 16 + r;
#pragma unroll
                for (int nt = 0; nt < 2; nt++) {
                    int n = nt * 8 + cq * 2;
                    *(float2*)&sgp[b0 * SG_STRIDE + n] =
                        make_float2(acc[mt][nt][0], acc[mt][nt][1]);
                    *(float2*)&sgp[(b0 + 8) * SG_STRIDE + n] =
                        make_float2(acc[mt][nt][2], acc[mt][nt][3]);
                }
            }
        }
        __syncthreads();

        {
            const float* sxb = sx + (t & 1) * 1024;
            float v[4];
#pragma unroll
            for (int g = 0; g < 4; g++) {
                int n = (g << 2) + ej;
                float s = sxb[eb * 16 + n];
#pragma unroll
                for (int w = 0; w < 8; w++) s += sg[w * SG_WARP + eb * SG_STRIDE + n];
                v[g] = s;
            }
            float si = 1.f / (1.f + __expf(-v[0]));
            float sf = 1.f / (1.f + __expf(-v[1]));
            float tg = tanhf(v[2]);
            float so = 1.f / (1.f + __expf(-v[3]));
            c_reg = sf * c_reg + si * tg;
            float hn = so * tanhf(c_reg);

            g_hbuf[(t + 1) & 1][(colj << 6) + eb] = hn;

            if (t == T_ - 1) {
                out[eb * H_ + colj]           = c_reg;   // c_fin
                out[B_ * H_ + eb * H_ + colj] = hn;      // h_fin
            }
        }

        __syncthreads();
        {
            unsigned tgt = base + 2 + (unsigned)t;
            if (tid == 0) st_rel(&g_flags[cta * 32], tgt);
            if (tid < NCTA)
                while ((int)(ld_acq(&g_flags[tid * 32]) - tgt) < 0) {}
            __syncthreads();
        }
    }
}

// ---------------------------------------------------------------------------
extern "C" void kernel_launch(void* const* d_in, const int* in_sizes, int n_in,
                              void* d_out, int out_size)
{
    const float* inputs = (const float*)d_in[0];  // [B, T, F]
    const float* Wx     = (const float*)d_in[1];  // [F, 4H]
    const float* Wh     = (const float*)d_in[2];  // [H, 4H]
    const float* bias   = (const float*)d_in[3];  // [4H]
    float* out = (float*)d_out;                   // [2, B, H] = (c_fin, h_fin)

    (void)in_sizes; (void)n_in; (void)out_size;

    conv_a<<<8192, 256>>>(inputs);
    conv_b<<<4096, 256>>>(Wx);

    cudaFuncSetAttribute(gemm_f16, cudaFuncAttributeMaxDynamicSharedMemorySize, GSMEM);
    gemm_f16<<<dim3(G4_ / 128, (B_ * T_) / 128), 256, GSMEM>>>(bias);

    const int lstm_smem = (3 * SH_CHUNK + 8 * SG_WARP + 2 * 1024) * (int)sizeof(float); // 155648 B
    cudaFuncSetAttribute(lstm_kernel, cudaFuncAttributeMaxDynamicSharedMemorySize, lstm_smem);
    lstm_kernel<<<NCTA, 256, lstm_smem>>>(Wh, out);
}

// round 10
// speedup vs baseline: 1.2078x; 1.0494x over previous
#include <cuda_runtime.h>
#include <cuda_fp16.h>
#include <cstdint>
#include <cstddef>

#define B_  64
#define T_  1024
#define F_  512
#define H_  512
#define G4_ 2048   // 4H
#define NCTA 128

__device__ float  g_xproj[(size_t)T_ * B_ * G4_];        // [t][b][col] fp32
__device__ float  g_hbuf[2][H_ * B_];                    // [col(k)][b] fp32, double-buffered
__device__ unsigned g_flags[NCTA * 32];                  // 1 flag per 128B line
__device__ __half g_ah[(size_t)B_ * T_ * F_];            // inputs as fp16 [m][k]
__device__ __half g_bh[(size_t)G4_ * F_];                // Wx^T fp16 [n][k]

// ---------------------------------------------------------------------------
// helpers
// ---------------------------------------------------------------------------
__device__ __forceinline__ void cp16(void* dst, const void* src)
{
    unsigned d = (unsigned)__cvta_generic_to_shared(dst);
    asm volatile("cp.async.cg.shared.global [%0], [%1], 16;" :: "r"(d), "l"(src) : "memory");
}

__device__ __forceinline__ unsigned ld_acq(const unsigned* p)
{
    unsigned v;
    asm volatile("ld.acquire.gpu.global.u32 %0, [%1];" : "=r"(v) : "l"(p) : "memory");
    return v;
}

__device__ __forceinline__ void st_rel(unsigned* p, unsigned v)
{
    asm volatile("st.release.gpu.global.u32 [%0], %1;" :: "l"(p), "r"(v) : "memory");
}

__device__ __forceinline__ unsigned pack2(float a, float b)
{
    __half2 h = __floats2half2_rn(a, b);
    return *(unsigned*)&h;
}

// lo part of the tf32 split: x - truncate_to_tf32(x)  (exact in fp32)
__device__ __forceinline__ float tf32_lo(float x)
{
    unsigned u = __float_as_uint(x) & 0xFFFFE000u;
    return x - __uint_as_float(u);
}

__device__ __forceinline__ void mma8(float* c,
    unsigned a0, unsigned a1, unsigned a2, unsigned a3,
    unsigned b0, unsigned b1)
{
    asm volatile(
        "mma.sync.aligned.m16n8k8.row.col.f32.tf32.tf32.f32 "
        "{%0,%1,%2,%3}, {%4,%5,%6,%7}, {%8,%9}, {%0,%1,%2,%3};"
        : "+f"(c[0]), "+f"(c[1]), "+f"(c[2]), "+f"(c[3])
        : "r"(a0), "r"(a1), "r"(a2), "r"(a3), "r"(b0), "r"(b1));
}

__device__ __forceinline__ void mma16(float* c,
    unsigned a0, unsigned a1, unsigned a2, unsigned a3,
    unsigned b0, unsigned b1)
{
    asm volatile(
        "mma.sync.aligned.m16n8k16.row.col.f32.f16.f16.f32 "
        "{%0,%1,%2,%3}, {%4,%5,%6,%7}, {%8,%9}, {%0,%1,%2,%3};"
        : "+f"(c[0]), "+f"(c[1]), "+f"(c[2]), "+f"(c[3])
        : "r"(a0), "r"(a1), "r"(a2), "r"(a3), "r"(b0), "r"(b1));
}

__device__ __forceinline__ void ldmx4(unsigned* r, unsigned addr)
{
    asm volatile(
        "ldmatrix.sync.aligned.m8n8.x4.shared.b16 {%0,%1,%2,%3}, [%4];"
        : "=r"(r[0]), "=r"(r[1]), "=r"(r[2]), "=r"(r[3]) : "r"(addr));
}

__device__ __forceinline__ uint32_t smem_to_u32(const void* p) {
    uint32_t a;
    asm("{ .reg .u64 t; cvta.to.shared.u64 t, %1; cvt.u32.u64 %0, t; }"
        : "=r"(a) : "l"(p));
    return a;
}

// ---------------------------------------------------------------------------
// Prep kernels: inputs -> fp16 [m][k]; Wx -> transposed fp16 [n][k]
// ---------------------------------------------------------------------------
__global__ void __launch_bounds__(256) conv_a(const float* __restrict__ A)
{
    unsigned i0 = blockIdx.x * 256 + threadIdx.x;
#pragma unroll
    for (int j = 0; j < 8; j++) {
        unsigned i = i0 + j * (8192u * 256u);
        float2 v = ((const float2*)A)[i];
        ((unsigned*)g_ah)[i] = pack2(v.x, v.y);
    }
}

__global__ void __launch_bounds__(256) conv_b(const float* __restrict__ W)
{
    unsigned i = blockIdx.x * 256 + threadIdx.x;
    int k = i >> 11, n = i & 2047;
    g_bh[(size_t)n * 512 + k] = __float2half_rn(W[i]);
}

// ---------------------------------------------------------------------------
// Kernel 1: x_proj = inputs @ Wx + bias — legacy fp16 mma, single B term,
// ldmatrix feeds, 4-stage cp.async ring, 1 syncthreads/stage, occupancy 2.
// CTA tile 128x128, 8 warps (2m x 4n), warp tile 64x32, k-stage = 32.
// smem rows: 32 halves @ 80B stride (conflict-free ldmatrix phases).
// Stage = A(10240) + B(10240) = 20480 B; 4 stages + 1KB hdr = 82944 B.
// ---------------------------------------------------------------------------
#define GROW 80                         // bytes per 32-half row
#define GTILE (128 * GROW)              // 10240 B
#define GSTAGE (2 * GTILE)              // 20480 B
#define GHDR 1024
#define GSMEM (GHDR + 4 * GSTAGE)       // 82944 B

__global__ void __launch_bounds__(256, 2) gemm_f16(const float* __restrict__ bias)
{
    extern __shared__ char smc[];
    const unsigned sm32 = smem_to_u32(smc);

    const int tid = threadIdx.x;
    const int n0  = blockIdx.x * 128;
    const int m0  = blockIdx.y * 128;
    const int warp = tid >> 5, lane = tid & 31;
    const int wm = warp & 1, wn = warp >> 1;
    const int r  = lane >> 2, cq = lane & 3;
    const int lr = lane & 15, lh = lane >> 4;      // ldmatrix row / halfsel

    float* sbias = (float*)smc;
    if (tid < 128) sbias[tid] = bias[n0 + tid];

    float acc[4][4][4];
#pragma unroll
    for (int i = 0; i < 4; i++)
#pragma unroll
        for (int j = 0; j < 4; j++)
#pragma unroll
            for (int k = 0; k < 4; k++) acc[i][j][k] = 0.f;

    auto issue = [&](int s) {
        char* base = smc + GHDR + (s & 3) * GSTAGE;
#pragma unroll
        for (int i = 0; i < 4; i++) {
            int idx  = tid + i * 256;        // 0..1023
            int tile = idx >> 9;             // 0=A 1=B
            int q    = idx & 511;
            int row  = q >> 2, seg = q & 3;
            const __half* src =
                (tile == 0) ? g_ah + (size_t)(m0 + row) * 512 + s * 32 + seg * 8 :
                              g_bh + (size_t)(n0 + row) * 512 + s * 32 + seg * 8;
            cp16(base + tile * GTILE + row * GROW + seg * 16, src);
        }
        asm volatile("cp.async.commit_group;" ::: "memory");
    };

    issue(0);
    issue(1);
    issue(2);

    for (int s = 0; s < 16; s++) {
        if (s <= 13)      { asm volatile("cp.async.wait_group 2;" ::: "memory"); }
        else if (s == 14) { asm volatile("cp.async.wait_group 1;" ::: "memory"); }
        else              { asm volatile("cp.async.wait_group 0;" ::: "memory"); }
        __syncthreads();
        if (s + 3 < 16) issue(s + 3);     // safe: sync => all mma(s-1) done

        const unsigned sb = sm32 + GHDR + (s & 3) * GSTAGE;
        const unsigned Aad = sb + (wm * 64 + lr) * GROW + lh * 16;
        const unsigned Bad = sb + GTILE + (wn * 32 + lr) * GROW + lh * 16;

#pragma unroll
        for (int kk = 0; kk < 2; kk++) {
            unsigned a[4][4];
#pragma unroll
            for (int mt = 0; mt < 4; mt++)
                ldmx4(a[mt], Aad + mt * 16 * GROW + kk * 32);

#pragma unroll
            for (int p = 0; p < 2; p++) {
                unsigned bq[4];
                ldmx4(bq, Bad + p * 16 * GROW + kk * 32);
#pragma unroll
                for (int mt = 0; mt < 4; mt++) {
                    mma16(acc[mt][2 * p],     a[mt][0], a[mt][1], a[mt][2], a[mt][3], bq[0], bq[2]);
                    mma16(acc[mt][2 * p + 1], a[mt][0], a[mt][1], a[mt][2], a[mt][3], bq[1], bq[3]);
                }
            }
        }
    }

    const int mbase = m0 + wm * 64;
    const int nbase = n0 + wn * 32;
#pragma unroll
    for (int nt = 0; nt < 4; nt++) {
        int nn = nbase + nt * 8 + cq * 2;
        float2 bb = *(const float2*)(sbias + nt * 8 + cq * 2 + wn * 32);
#pragma unroll
        for (int mt = 0; mt < 4; mt++) {
            int row0 = mbase + mt * 16 + r;
            int t0 = row0 & (T_ - 1), bi0 = row0 >> 10;
            float2 v0 = make_float2(acc[mt][nt][0] + bb.x, acc[mt][nt][1] + bb.y);
            *(float2*)&g_xproj[((size_t)(t0 * 64 + bi0) << 11) + nn] = v0;
            int row1 = row0 + 8;
            int t1 = row1 & (T_ - 1), bi1 = row1 >> 10;
            float2 v1 = make_float2(acc[mt][nt][2] + bb.x, acc[mt][nt][3] + bb.y);
            *(float2*)&g_xproj[((size_t)(t1 * 64 + bi1) << 11) + nn] = v1;
        }
    }
}

// ---------------------------------------------------------------------------
// Kernel 2: persistent LSTM recurrence — VERBATIM best-known R5 config.
// ---------------------------------------------------------------------------
#define SH_STRIDE 72
#define SH_CHUNK (128 * SH_STRIDE)
#define SG_STRIDE 18
#define SG_WARP  (64 * SG_STRIDE)

__global__ void __launch_bounds__(256, 1) lstm_kernel(
    const float* __restrict__ Wh,
    float* __restrict__ out)
{
    extern __shared__ float smem[];
    float* sh = smem;                    // 3 * 128*72 = 27648 floats
    float* sg = sh + 3 * SH_CHUNK;       // 8 * 64*18  =  9216 floats
    float* sx = sg + 8 * SG_WARP;        // 2 * 1024   =  2048 floats

    const int tid = threadIdx.x;
    const int cta = blockIdx.x;
    const int warp = tid >> 5, lane = tid & 31;
    const int r = lane >> 2, cq = lane & 3;

    const unsigned base = ld_acq(&g_flags[cta * 32]);

    unsigned BH[16][2], BL[16][2];
#pragma unroll
    for (int c = 0; c < 4; c++)
#pragma unroll
        for (int j = 0; j < 2; j++) {
            int kt = c * 16 + j * 8 + warp;
            int k0 = kt << 3;
#pragma unroll
            for (int nt = 0; nt < 2; nt++) {
                int n = nt * 8 + r;
                int col = ((n >> 2) << 9) + (cta << 2) + (n & 3);
                float w0 = Wh[(size_t)(k0 + cq) * G4_ + col];
                float w1 = Wh[(size_t)(k0 + cq + 4) * G4_ + col];
                int bi = (c << 2) | (j << 1) | nt;
                BH[bi][0] = __float_as_uint(w0);
                BH[bi][1] = __float_as_uint(w1);
                BL[bi][0] = __float_as_uint(tf32_lo(w0));
                BL[bi][1] = __float_as_uint(tf32_lo(w1));
            }
        }

    g_hbuf[0][(cta << 8) + tid] = 0.f;

    {
        int b = tid >> 2, g = tid & 3;
        cp16(sx + b * 16 + g * 4,
             g_xproj + ((size_t)b << 11) + ((size_t)g << 9) + (cta << 2));
        asm volatile("cp.async.commit_group;" ::: "memory");
        asm volatile("cp.async.wait_group 0;" ::: "memory");
    }

    __syncthreads();
    {   // barrier 0: init complete
        unsigned tgt = base + 1;
        if (tid == 0) st_rel(&g_flags[cta * 32], tgt);
        if (tid < NCTA)
            while ((int)(ld_acq(&g_flags[tid * 32]) - tgt) < 0) {}
        __syncthreads();
    }

    const int eb = tid >> 2, ej = tid & 3;
    const int colj = (cta << 2) + ej;
    float c_reg = 0.f;

    auto issue_chunk = [&](const float* hsrc, int ch) {
        const int buf = ch % 3;
#pragma unroll
        for (int j = 0; j < 2; j++) {
            const float* s0 = hsrc + (size_t)(ch * 128 + j * 64 + warp * 8) * 64;
            float* d0 = sh + buf * SH_CHUNK + (j * 64 + warp * 8) * SH_STRIDE;
#pragma unroll
            for (int i = 0; i < 4; i++) {
                int s_ = lane + 32 * i;
                int row8 = s_ >> 4, segc = s_ & 15;
                cp16(d0 + row8 * SH_STRIDE + segc * 4, s0 + row8 * 64 + segc * 4);
            }
        }
    };

    for (int t = 0; t < T_; t++) {
        const float* hsrc = g_hbuf[t & 1];

        issue_chunk(hsrc, 0);
        asm volatile("cp.async.commit_group;" ::: "memory");
        issue_chunk(hsrc, 1);
        asm volatile("cp.async.commit_group;" ::: "memory");

        float acc[4][2][4];
#pragma unroll
        for (int mt = 0; mt < 4; mt++)
#pragma unroll
            for (int nt = 0; nt < 2; nt++)
#pragma unroll
                for (int k = 0; k < 4; k++) acc[mt][nt][k] = 0.f;

#pragma unroll
        for (int ch = 0; ch < 4; ch++) {
            if (ch < 3) { asm volatile("cp.async.wait_group 1;" ::: "memory"); }
            else        { asm volatile("cp.async.wait_group 0;" ::: "memory"); }
            __syncwarp();

            if (ch == 0) {
                issue_chunk(hsrc, 2);
                if (t + 1 < T_) {
                    int b = tid >> 2, g = tid & 3;
                    cp16(sx + ((t + 1) & 1) * 1024 + b * 16 + g * 4,
                         g_xproj + ((size_t)((t + 1) * 64 + b) << 11)
                                 + ((size_t)g << 9) + (cta << 2));
                }
                asm volatile("cp.async.commit_group;" ::: "memory");
            } else if (ch == 1) {
                issue_chunk(hsrc, 3);
                asm volatile("cp.async.commit_group;" ::: "memory");
            }

            const float* hb = sh + (ch % 3) * SH_CHUNK;
#pragma unroll
            for (int j = 0; j < 2; j++) {
                const int lk0 = ((j << 3) + warp) << 3;
                unsigned a[4][4];
#pragma unroll
                for (int mt = 0; mt < 4; mt++) {
                    const float* ap = hb + (lk0 + cq) * SH_STRIDE + mt * 16 + r;
                    a[mt][0] = __float_as_uint(ap[0]);
                    a[mt][1] = __float_as_uint(ap[8]);
                    a[mt][2] = __float_as_uint(ap[4 * SH_STRIDE]);
                    a[mt][3] = __float_as_uint(ap[4 * SH_STRIDE + 8]);
                }
                const int bi0 = (ch << 2) | (j << 1);
#pragma unroll
                for (int nt = 0; nt < 2; nt++)
#pragma unroll
                    for (int mt = 0; mt < 4; mt++)
                        mma8(acc[mt][nt], a[mt][0], a[mt][1], a[mt][2], a[mt][3],
                             BH[bi0 | nt][0], BH[bi0 | nt][1]);
#pragma unroll
                for (int nt = 0; nt < 2; nt++)
#pragma unroll
                    for (int mt = 0; mt < 4; mt++)
                        mma8(acc[mt][nt], a[mt][0], a[mt][1], a[mt][2], a[mt][3],
                             BL[bi0 | nt][0], BL[bi0 | nt][1]);
            }
        }

        {
            float* sgp = sg + warp * SG_WARP;
#pragma unroll
            for (int mt = 0; mt < 4; mt++) {
                int b0 = mt * 16 + r;
#pragma unroll
                for (int nt = 0; nt < 2; nt++) {
                    int n = nt * 8 + cq * 2;
                    *(float2*)&sgp[b0 * SG_STRIDE + n] =
                        make_float2(acc[mt][nt][0], acc[mt][nt][1]);
                    *(float2*)&sgp[(b0 + 8) * SG_STRIDE + n] =
                        make_float2(acc[mt][nt][2], acc[mt][nt][3]);
                }
            }
        }
        __syncthreads();

        {
            const float* sxb = sx + (t & 1) * 1024;
            float v[4];
#pragma unroll
            for (int g = 0; g < 4; g++) {
                int n = (g << 2) + ej;
                float s = sxb[eb * 16 + n];
#pragma unroll
                for (int w = 0; w < 8; w++) s += sg[w * SG_WARP + eb * SG_STRIDE + n];
                v[g] = s;
            }
            float si = 1.f / (1.f + __expf(-v[0]));
            float sf = 1.f / (1.f + __expf(-v[1]));
            float tg = tanhf(v[2]);
            float so = 1.f / (1.f + __expf(-v[3]));
            c_reg = sf * c_reg + si * tg;
            float hn = so * tanhf(c_reg);

            g_hbuf[(t + 1) & 1][(colj << 6) + eb] = hn;

            if (t == T_ - 1) {
                out[eb * H_ + colj]           = c_reg;   // c_fin
                out[B_ * H_ + eb * H_ + colj] = hn;      // h_fin
            }
        }

        __syncthreads();
        {
            unsigned tgt = base + 2 + (unsigned)t;
            if (tid == 0) st_rel(&g_flags[cta * 32], tgt);
            if (tid < NCTA)
                while ((int)(ld_acq(&g_flags[tid * 32]) - tgt) < 0) {}
            __syncthreads();
        }
    }
}

// ---------------------------------------------------------------------------
extern "C" void kernel_launch(void* const* d_in, const int* in_sizes, int n_in,
                              void* d_out, int out_size)
{
    const float* inputs = (const float*)d_in[0];  // [B, T, F]
    const float* Wx     = (const float*)d_in[1];  // [F, 4H]
    const float* Wh     = (const float*)d_in[2];  // [H, 4H]
    const float* bias   = (const float*)d_in[3];  // [4H]
    float* out = (float*)d_out;                   // [2, B, H] = (c_fin, h_fin)

    (void)in_sizes; (void)n_in; (void)out_size;

    conv_a<<<8192, 256>>>(inputs);
    conv_b<<<4096, 256>>>(Wx);

    cudaFuncSetAttribute(gemm_f16, cudaFuncAttributeMaxDynamicSharedMemorySize, GSMEM);
    gemm_f16<<<dim3(G4_ / 128, (B_ * T_) / 128), 256, GSMEM>>>(bias);

    const int lstm_smem = (3 * SH_CHUNK + 8 * SG_WARP + 2 * 1024) * (int)sizeof(float); // 155648 B
    cudaFuncSetAttribute(lstm_kernel, cudaFuncAttributeMaxDynamicSharedMemorySize, lstm_smem);
    lstm_kernel<<<NCTA, 256, lstm_smem>>>(Wh, out);
}